// round 10
// baseline (speedup 1.0000x reference)
#include <cuda_runtime.h>
#include <cuda_bf16.h>
#include <cstdint>

// Problem constants: B=16, H=4, W=900, C=256 -> D = H*C = 1024
#define PB 16
#define PH 4
#define PW 900
#define PC 256
#define PD 1024

#define TM 128            // gram i-tile
#define TN 256            // gram j-tile
#define BK 64             // K elems per chunk (64 bf16 = 128B)
#define NCHP 16           // chunks per pass (1024/64)
#define NPASS 3           // hi*hi, hi*lo, lo*hi
#define TOTCH (NCHP*NPASS)   // 48
#define NST 3             // pipeline stages (2 in flight)
#define NT 256            // threads: 8 warps, 2x4 grid, warp tile 64x64

// smem: staged A/B tiles, 144B row stride (128B data + 16B pad -> conflict-free ldmatrix)
#define ROWB   144
#define STG_A  (TM*ROWB)              // 18432
#define STG_B  (TN*ROWB)              // 36864
#define STG_SZ (STG_A + STG_B)        // 55296
// epilogue fp32 tile: 128 rows x 260 floats (reuses stage smem)
#define TPAD   260
#define SM_TOTAL (NST*STG_SZ)         // 165888 (> 128*260*4 = 133120)

// bf16 split scratch: [B][W][D] rows of 1024 bf16 (2048B)
__device__ __nv_bfloat16 g_x1h[(size_t)PB*PW*PD];
__device__ __nv_bfloat16 g_x1l[(size_t)PB*PW*PD];
__device__ __nv_bfloat16 g_x2h[(size_t)PB*PW*PD];
__device__ __nv_bfloat16 g_x2l[(size_t)PB*PW*PD];

__device__ __forceinline__ uint32_t smem_u32(const void* p) {
    uint32_t a;
    asm("{ .reg .u64 t; cvta.to.shared.u64 t, %1; cvt.u32.u64 %0, t; }" : "=r"(a) : "l"(p));
    return a;
}
__device__ __forceinline__ void cp_async16(uint32_t dst, const void* src, int szbytes) {
    asm volatile("cp.async.cg.shared.global [%0], [%1], 16, %2;"
                 :: "r"(dst), "l"(src), "r"(szbytes) : "memory");
}
#define CP_COMMIT() asm volatile("cp.async.commit_group;" ::: "memory")
#define CP_WAIT1()  asm volatile("cp.async.wait_group 1;" ::: "memory")
#define CP_WAIT0()  asm volatile("cp.async.wait_group 0;" ::: "memory")

__device__ __forceinline__ void ldsm4(uint32_t* r, uint32_t addr) {
    asm volatile("ldmatrix.sync.aligned.m8n8.x4.shared.b16 {%0,%1,%2,%3}, [%4];"
                 : "=r"(r[0]), "=r"(r[1]), "=r"(r[2]), "=r"(r[3]) : "r"(addr));
}
__device__ __forceinline__ void mma_bf16(float* d, const uint32_t* a, const uint32_t* b) {
    asm volatile("mma.sync.aligned.m16n8k16.row.col.f32.bf16.bf16.f32 "
                 "{%0,%1,%2,%3}, {%4,%5,%6,%7}, {%8,%9}, {%0,%1,%2,%3};"
                 : "+f"(d[0]), "+f"(d[1]), "+f"(d[2]), "+f"(d[3])
                 : "r"(a[0]), "r"(a[1]), "r"(a[2]), "r"(a[3]), "r"(b[0]), "r"(b[1]));
}

// ---------------- utility kernels ----------------
__global__ void zero_out_kernel(float* __restrict__ out, int n) {
    int i = blockIdx.x * blockDim.x + threadIdx.x;
    if (i < n) out[i] = 0.0f;
}

// fused convert: splits BOTH inputs to bf16 hi/lo in [B][W][D] layout
__global__ void convert_kernel(const float4* __restrict__ x1, const float4* __restrict__ x2) {
    size_t t = (size_t)blockIdx.x * blockDim.x + threadIdx.x;
    size_t n4 = (size_t)PB * PH * PW * PC / 4;
    if (t >= n4) return;
    size_t f = t * 4;
    int c = (int)(f & 255);
    size_t rest = f >> 8;                 // (b*PH + h)*PW + w
    int w = (int)(rest % PW);
    size_t rest2 = rest / PW;             // b*PH + h
    int h = (int)(rest2 & 3);
    int b = (int)(rest2 >> 2);
    size_t o = ((size_t)b * PW + w) * PD + (size_t)h * PC + c;

#pragma unroll
    for (int which = 0; which < 2; which++) {
        float4 v = (which == 0) ? x1[t] : x2[t];
        __nv_bfloat16 h0 = __float2bfloat16(v.x), h1 = __float2bfloat16(v.y);
        __nv_bfloat16 h2 = __float2bfloat16(v.z), h3 = __float2bfloat16(v.w);
        __nv_bfloat16 l0 = __float2bfloat16(v.x - __bfloat162float(h0));
        __nv_bfloat16 l1 = __float2bfloat16(v.y - __bfloat162float(h1));
        __nv_bfloat16 l2 = __float2bfloat16(v.z - __bfloat162float(h2));
        __nv_bfloat16 l3 = __float2bfloat16(v.w - __bfloat162float(h3));
        __nv_bfloat16* hi = (which == 0) ? g_x1h : g_x2h;
        __nv_bfloat16* lo = (which == 0) ? g_x1l : g_x2l;
        *reinterpret_cast<__nv_bfloat162*>(hi + o)     = __nv_bfloat162(h0, h1);
        *reinterpret_cast<__nv_bfloat162*>(hi + o + 2) = __nv_bfloat162(h2, h3);
        *reinterpret_cast<__nv_bfloat162*>(lo + o)     = __nv_bfloat162(l0, l1);
        *reinterpret_cast<__nv_bfloat162*>(lo + o + 2) = __nv_bfloat162(l2, l3);
    }
}

// ---------------- main GEMM + band-reduce kernel ----------------
__global__ __launch_bounds__(NT, 1)
void gemm_band_kernel(float* __restrict__ out) {
    extern __shared__ __align__(128) char smem[];
    uint32_t sb = smem_u32(smem);
    const int tid  = threadIdx.x;
    const int wid  = tid >> 5;
    const int lane = tid & 31;
    const int b  = blockIdx.z;
    const int i0 = blockIdx.y * TM;
    const int j0 = blockIdx.x * TN;
    const int validA = min(TM, PW - i0);
    const int validB = min(TN, PW - j0);

    const int wm = wid >> 2;          // 0..1  (m 64-row half)
    const int wn = wid & 3;           // 0..3  (n 64-col quarter)

    // ldmatrix per-lane address components
    const uint32_t a_row = (uint32_t)(wm * 64 + (lane & 7) + ((lane >> 3) & 1) * 8);
    const uint32_t a_kh  = (uint32_t)(((lane >> 4) & 1) * 16);
    const uint32_t b_row = (uint32_t)(wn * 64 + (lane & 7) + ((lane >> 4) & 1) * 8);
    const uint32_t b_kh  = (uint32_t)(((lane >> 3) & 1) * 16);

    float acc[4][8][4];
#pragma unroll
    for (int fm = 0; fm < 4; fm++)
#pragma unroll
        for (int fn = 0; fn < 8; fn++)
#pragma unroll
            for (int e = 0; e < 4; e++) acc[fm][fn][e] = 0.0f;

    // double-buffered fragments (the point of this round)
    uint32_t af[2][4][4], bq[2][4][4];

    // chunk loader: chunk ch = pass*NCHP + kc ; 48KB per chunk, 12 cp.async/thread
    auto load_chunk = [&](int ch, int st) {
        const int p  = ch >> 4;           // pass
        const int kc = ch & 15;           // k-chunk within pass
        const char* Ab = (const char*)((p == 2 ? g_x1l : g_x1h) + ((size_t)b * PW + i0) * PD) + kc * 128;
        const char* Bb = (const char*)((p == 1 ? g_x2l : g_x2h) + ((size_t)b * PW + j0) * PD) + kc * 128;
        const uint32_t sA = sb + (uint32_t)st * STG_SZ;
        const uint32_t sB = sA + STG_A;
#pragma unroll
        for (int itr = 0; itr < 4; itr++) {               // A: 128 rows x 8 granules
            int e = itr * NT + tid;
            int r = e >> 3, c = e & 7;
            int rr = (r < validA) ? r : 0;
            cp_async16(sA + r * ROWB + c * 16, Ab + (size_t)rr * 2048 + c * 16,
                       (r < validA) ? 16 : 0);
        }
#pragma unroll
        for (int itr = 0; itr < 8; itr++) {               // B: 256 rows x 8 granules
            int e = itr * NT + tid;
            int r = e >> 3, c = e & 7;
            int rr = (r < validB) ? r : 0;
            cp_async16(sB + r * ROWB + c * 16, Bb + (size_t)rr * 2048 + c * 16,
                       (r < validB) ? 16 : 0);
        }
        CP_COMMIT();
    };

    // fragment loader for one k-step (K=16 -> 32B offset per ks)
    auto ldsm_step = [&](int buf, uint32_t sA, uint32_t sB, int ks) {
#pragma unroll
        for (int fm = 0; fm < 4; fm++)
            ldsm4(af[buf][fm], sA + (a_row + fm * 16) * ROWB + ks * 32 + a_kh);
#pragma unroll
        for (int f2 = 0; f2 < 4; f2++)
            ldsm4(bq[buf][f2], sB + (b_row + f2 * 16) * ROWB + ks * 32 + b_kh);
    };

    // prologue: 2 chunks in flight
    load_chunk(0, 0);
    load_chunk(1, 1);

    for (int it = 0; it < TOTCH; it++) {
        const int st = it % NST;
        if (it < TOTCH - 1) CP_WAIT1(); else CP_WAIT0();
        __syncthreads();

        if (it + 2 < TOTCH) load_chunk(it + 2, (it + 2) % NST);

        const uint32_t sA = sb + (uint32_t)st * STG_SZ;
        const uint32_t sB = sA + STG_A;

        ldsm_step(0, sA, sB, 0);
#pragma unroll
        for (int ks = 0; ks < 4; ks++) {                  // 4 x K=16 per 64-chunk
            if (ks < 3) ldsm_step((ks + 1) & 1, sA, sB, ks + 1);  // prefetch next step
            const int cur = ks & 1;
#pragma unroll
            for (int fm = 0; fm < 4; fm++)
#pragma unroll
                for (int fn = 0; fn < 8; fn++)
                    mma_bf16(acc[fm][fn], af[cur][fm], &bq[cur][fn >> 1][(fn & 1) * 2]);
        }
    }

    // ---- epilogue: write fp32 tile to smem, then diagonal band-reduce ----
    __syncthreads();   // all warps done reading stage smem
    float* tile = reinterpret_cast<float*>(smem);
    const int g = lane >> 2;
    const int t2 = (lane & 3) * 2;
    const int mb = wm * 64, nb = wn * 64;
#pragma unroll
    for (int fm = 0; fm < 4; fm++) {
        const int m = mb + fm * 16 + g;
#pragma unroll
        for (int fn = 0; fn < 8; fn++) {
            const int n = nb + fn * 8 + t2;
            tile[m * TPAD + n]           = acc[fm][fn][0];
            tile[m * TPAD + n + 1]       = acc[fm][fn][1];
            tile[(m + 8) * TPAD + n]     = acc[fm][fn][2];
            tile[(m + 8) * TPAD + n + 1] = acc[fm][fn][3];
        }
    }
    __syncthreads();

    // 383 diagonals: delta = m - n in [-255, 127]
    for (int d = tid; d < 383; d += NT) {
        const int delta = d - 255;
        const int mlo = max(0, delta);
        const int mhi = min(TM - 1, TN - 1 + delta);
        float s = 0.0f;
        for (int m = mlo; m <= mhi; m++) s += tile[m * TPAD + (m - delta)];
        if (s != 0.0f) {
            const int dg = (i0 - j0) + delta;            // global i - j
            const int sidx = (dg + 450 + 1800) % 900;    // (i - j + 450) mod 900
            atomicAdd(&out[b * PW + sidx], s);
        }
    }
}

// ---------------- host launcher ----------------
extern "C" void kernel_launch(void* const* d_in, const int* in_sizes, int n_in,
                              void* d_out, int out_size) {
    const float4* x1 = (const float4*)d_in[0];
    const float4* x2 = (const float4*)d_in[1];
    float* out = (float*)d_out;

    cudaFuncSetAttribute(gemm_band_kernel,
                         cudaFuncAttributeMaxDynamicSharedMemorySize, SM_TOTAL);

    const int n_out = PB * PW;  // 14400
    zero_out_kernel<<<(n_out + 255) / 256, 256>>>(out, n_out);

    const size_t n4 = (size_t)PB * PH * PW * PC / 4;  // 3,686,400
    convert_kernel<<<(int)((n4 + 255) / 256), 256>>>(x1, x2);

    dim3 grid((PW + TN - 1) / TN,   // 4 j-tiles
              (PW + TM - 1) / TM,   // 8 i-tiles
              PB);                  // 16 batches
    gemm_band_kernel<<<grid, NT, SM_TOTAL>>>(out);
}

// round 12
// speedup vs baseline: 1.2554x; 1.2554x over previous
#include <cuda_runtime.h>
#include <cuda_bf16.h>
#include <cstdint>

// Problem constants: B=16, H=4, W=900, C=256 -> D = H*C = 1024
#define PB 16
#define PH 4
#define PW 900
#define PC 256
#define PD 1024

#define TM 128            // gram i-tile
#define TN 128            // gram j-tile
#define BK 64             // K elems per chunk (64 bf16 = 128B)
#define NCHP 16           // chunks per pass (1024/64)
#define NPASS 3           // hi*hi, hi*lo, lo*hi
#define TOTCH (NCHP*NPASS)   // 48
#define NST 3             // pipeline stages (2 in flight)
#define NT 256            // threads: 8 warps, 2x4 grid, warp tile 64x32

// smem: staged A/B tiles, 144B row stride (128B data + 16B pad -> conflict-free ldmatrix)
#define ROWB   144
#define STG_A  (TM*ROWB)              // 18432
#define STG_B  (TN*ROWB)              // 18432
#define STG_SZ (STG_A + STG_B)        // 36864
// epilogue fp32 tile: 128 rows x 132 floats (reuses stage smem)
#define TPAD   132
#define SM_TOTAL (NST*STG_SZ)         // 110592 (> 128*132*4 = 67584) ; 2 CTAs = 221184 <= SM limit

// bf16 split scratch: [B][W][D] rows of 1024 bf16 (2048B)
__device__ __nv_bfloat16 g_x1h[(size_t)PB*PW*PD];
__device__ __nv_bfloat16 g_x1l[(size_t)PB*PW*PD];
__device__ __nv_bfloat16 g_x2h[(size_t)PB*PW*PD];
__device__ __nv_bfloat16 g_x2l[(size_t)PB*PW*PD];

__device__ __forceinline__ uint32_t smem_u32(const void* p) {
    uint32_t a;
    asm("{ .reg .u64 t; cvta.to.shared.u64 t, %1; cvt.u32.u64 %0, t; }" : "=r"(a) : "l"(p));
    return a;
}
__device__ __forceinline__ void cp_async16(uint32_t dst, const void* src, int szbytes) {
    asm volatile("cp.async.cg.shared.global [%0], [%1], 16, %2;"
                 :: "r"(dst), "l"(src), "r"(szbytes) : "memory");
}
#define CP_COMMIT() asm volatile("cp.async.commit_group;" ::: "memory")
#define CP_WAIT1()  asm volatile("cp.async.wait_group 1;" ::: "memory")
#define CP_WAIT0()  asm volatile("cp.async.wait_group 0;" ::: "memory")

__device__ __forceinline__ void ldsm4(uint32_t* r, uint32_t addr) {
    asm volatile("ldmatrix.sync.aligned.m8n8.x4.shared.b16 {%0,%1,%2,%3}, [%4];"
                 : "=r"(r[0]), "=r"(r[1]), "=r"(r[2]), "=r"(r[3]) : "r"(addr));
}
__device__ __forceinline__ void mma_bf16(float* d, const uint32_t* a, const uint32_t* b) {
    asm volatile("mma.sync.aligned.m16n8k16.row.col.f32.bf16.bf16.f32 "
                 "{%0,%1,%2,%3}, {%4,%5,%6,%7}, {%8,%9}, {%0,%1,%2,%3};"
                 : "+f"(d[0]), "+f"(d[1]), "+f"(d[2]), "+f"(d[3])
                 : "r"(a[0]), "r"(a[1]), "r"(a[2]), "r"(a[3]), "r"(b[0]), "r"(b[1]));
}

// ---------------- utility kernels ----------------
__global__ void zero_out_kernel(float* __restrict__ out, int n) {
    int i = blockIdx.x * blockDim.x + threadIdx.x;
    if (i < n) out[i] = 0.0f;
}

// fused convert: splits BOTH inputs to bf16 hi/lo in [B][W][D] layout
__global__ void convert_kernel(const float4* __restrict__ x1, const float4* __restrict__ x2) {
    size_t t = (size_t)blockIdx.x * blockDim.x + threadIdx.x;
    size_t n4 = (size_t)PB * PH * PW * PC / 4;
    if (t >= n4) return;
    size_t f = t * 4;
    int c = (int)(f & 255);
    size_t rest = f >> 8;                 // (b*PH + h)*PW + w
    int w = (int)(rest % PW);
    size_t rest2 = rest / PW;             // b*PH + h
    int h = (int)(rest2 & 3);
    int b = (int)(rest2 >> 2);
    size_t o = ((size_t)b * PW + w) * PD + (size_t)h * PC + c;

#pragma unroll
    for (int which = 0; which < 2; which++) {
        float4 v = (which == 0) ? x1[t] : x2[t];
        __nv_bfloat16 h0 = __float2bfloat16(v.x), h1 = __float2bfloat16(v.y);
        __nv_bfloat16 h2 = __float2bfloat16(v.z), h3 = __float2bfloat16(v.w);
        __nv_bfloat16 l0 = __float2bfloat16(v.x - __bfloat162float(h0));
        __nv_bfloat16 l1 = __float2bfloat16(v.y - __bfloat162float(h1));
        __nv_bfloat16 l2 = __float2bfloat16(v.z - __bfloat162float(h2));
        __nv_bfloat16 l3 = __float2bfloat16(v.w - __bfloat162float(h3));
        __nv_bfloat16* hi = (which == 0) ? g_x1h : g_x2h;
        __nv_bfloat16* lo = (which == 0) ? g_x1l : g_x2l;
        *reinterpret_cast<__nv_bfloat162*>(hi + o)     = __nv_bfloat162(h0, h1);
        *reinterpret_cast<__nv_bfloat162*>(hi + o + 2) = __nv_bfloat162(h2, h3);
        *reinterpret_cast<__nv_bfloat162*>(lo + o)     = __nv_bfloat162(l0, l1);
        *reinterpret_cast<__nv_bfloat162*>(lo + o + 2) = __nv_bfloat162(l2, l3);
    }
}

// ---------------- main GEMM + band-reduce kernel: 2 CTAs/SM ----------------
__global__ __launch_bounds__(NT, 2)
void gemm_band_kernel(float* __restrict__ out) {
    extern __shared__ __align__(128) char smem[];
    uint32_t sb = smem_u32(smem);
    const int tid  = threadIdx.x;
    const int wid  = tid >> 5;
    const int lane = tid & 31;
    const int b  = blockIdx.z;
    const int i0 = blockIdx.y * TM;
    const int j0 = blockIdx.x * TN;
    const int validA = min(TM, PW - i0);
    const int validB = min(TN, PW - j0);

    const int wm = wid >> 2;          // 0..1  (m 64-row half)
    const int wn = wid & 3;           // 0..3  (n 32-col slice)

    // ldmatrix per-lane address components
    const uint32_t a_row = (uint32_t)(wm * 64 + (lane & 7) + ((lane >> 3) & 1) * 8);
    const uint32_t a_kh  = (uint32_t)(((lane >> 4) & 1) * 16);
    const uint32_t b_row = (uint32_t)(wn * 32 + (lane & 7) + ((lane >> 4) & 1) * 8);
    const uint32_t b_kh  = (uint32_t)(((lane >> 3) & 1) * 16);

    float acc[4][4][4];
#pragma unroll
    for (int fm = 0; fm < 4; fm++)
#pragma unroll
        for (int fn = 0; fn < 4; fn++)
#pragma unroll
            for (int e = 0; e < 4; e++) acc[fm][fn][e] = 0.0f;

    // chunk loader: chunk ch = pass*NCHP + kc ; 32KB per chunk, 8 cp.async/thread
    auto load_chunk = [&](int ch, int st) {
        const int p  = ch >> 4;           // pass
        const int kc = ch & 15;           // k-chunk within pass
        const char* Ab = (const char*)((p == 2 ? g_x1l : g_x1h) + ((size_t)b * PW + i0) * PD) + kc * 128;
        const char* Bb = (const char*)((p == 1 ? g_x2l : g_x2h) + ((size_t)b * PW + j0) * PD) + kc * 128;
        const uint32_t sA = sb + (uint32_t)st * STG_SZ;
        const uint32_t sB = sA + STG_A;
#pragma unroll
        for (int itr = 0; itr < 4; itr++) {               // A: 128 rows x 8 granules
            int e = itr * NT + tid;
            int r = e >> 3, c = e & 7;
            int rr = (r < validA) ? r : 0;
            cp_async16(sA + r * ROWB + c * 16, Ab + (size_t)rr * 2048 + c * 16,
                       (r < validA) ? 16 : 0);
        }
#pragma unroll
        for (int itr = 0; itr < 4; itr++) {               // B: 128 rows x 8 granules
            int e = itr * NT + tid;
            int r = e >> 3, c = e & 7;
            int rr = (r < validB) ? r : 0;
            cp_async16(sB + r * ROWB + c * 16, Bb + (size_t)rr * 2048 + c * 16,
                       (r < validB) ? 16 : 0);
        }
        CP_COMMIT();
    };

    // prologue: 2 chunks in flight
    load_chunk(0, 0);
    load_chunk(1, 1);

    for (int it = 0; it < TOTCH; it++) {
        const int st = it % NST;
        if (it < TOTCH - 1) CP_WAIT1(); else CP_WAIT0();
        __syncthreads();

        if (it + 2 < TOTCH) load_chunk(it + 2, (it + 2) % NST);

        const uint32_t sA = sb + (uint32_t)st * STG_SZ;
        const uint32_t sB = sA + STG_A;
#pragma unroll
        for (int ks = 0; ks < 4; ks++) {                  // 4 x K=16 per 64-chunk
            uint32_t af[4][4], bq[2][4];
#pragma unroll
            for (int fm = 0; fm < 4; fm++)
                ldsm4(af[fm], sA + (a_row + fm * 16) * ROWB + ks * 32 + a_kh);
#pragma unroll
            for (int f2 = 0; f2 < 2; f2++)
                ldsm4(bq[f2], sB + (b_row + f2 * 16) * ROWB + ks * 32 + b_kh);
#pragma unroll
            for (int fm = 0; fm < 4; fm++)
#pragma unroll
                for (int fn = 0; fn < 4; fn++)
                    mma_bf16(acc[fm][fn], af[fm], &bq[fn >> 1][(fn & 1) * 2]);
        }
    }

    // ---- epilogue: write fp32 tile to smem, then diagonal band-reduce ----
    __syncthreads();   // all warps done reading stage smem
    float* tile = reinterpret_cast<float*>(smem);
    const int g = lane >> 2;
    const int t2 = (lane & 3) * 2;
    const int mb = wm * 64, nb = wn * 32;
#pragma unroll
    for (int fm = 0; fm < 4; fm++) {
        const int m = mb + fm * 16 + g;
#pragma unroll
        for (int fn = 0; fn < 4; fn++) {
            const int n = nb + fn * 8 + t2;
            tile[m * TPAD + n]           = acc[fm][fn][0];
            tile[m * TPAD + n + 1]       = acc[fm][fn][1];
            tile[(m + 8) * TPAD + n]     = acc[fm][fn][2];
            tile[(m + 8) * TPAD + n + 1] = acc[fm][fn][3];
        }
    }
    __syncthreads();

    // 255 diagonals: delta = m - n in [-127, 127]
    if (tid < 255) {
        const int delta = tid - 127;
        const int mlo = max(0, delta);
        const int mhi = min(TM - 1, TN - 1 + delta);
        float s = 0.0f;
        for (int m = mlo; m <= mhi; m++) s += tile[m * TPAD + (m - delta)];
        if (s != 0.0f) {
            const int dg = (i0 - j0) + delta;            // global i - j
            const int sidx = (dg + 450 + 1800) % 900;    // (i - j + 450) mod 900
            atomicAdd(&out[b * PW + sidx], s);
        }
    }
}

// ---------------- host launcher ----------------
extern "C" void kernel_launch(void* const* d_in, const int* in_sizes, int n_in,
                              void* d_out, int out_size) {
    const float4* x1 = (const float4*)d_in[0];
    const float4* x2 = (const float4*)d_in[1];
    float* out = (float*)d_out;

    cudaFuncSetAttribute(gemm_band_kernel,
                         cudaFuncAttributeMaxDynamicSharedMemorySize, SM_TOTAL);

    const int n_out = PB * PW;  // 14400
    zero_out_kernel<<<(n_out + 255) / 256, 256>>>(out, n_out);

    const size_t n4 = (size_t)PB * PH * PW * PC / 4;  // 3,686,400
    convert_kernel<<<(int)((n4 + 255) / 256), 256>>>(x1, x2);

    dim3 grid((PW + TN - 1) / TN,   // 8 j-tiles
              (PW + TM - 1) / TM,   // 8 i-tiles
              PB);                  // 16 batches
    gemm_band_kernel<<<grid, NT, SM_TOTAL>>>(out);
}